// round 14
// baseline (speedup 1.0000x reference)
#include <cuda_runtime.h>

#define cN 50000
#define cE 500000
#define cF 256
#define cED 64
#define cH 128
#define cO 32
#define NEG 0.2f
#define EPSc 1e-16f

// ---------------- scratch (device globals; no allocation allowed) ----------------
__device__ float g_h1[cN * cH];      // layer1 h = x@W1
__device__ float g_h2[cN * cO];      // layer2 h = relu(x1)@W2
__device__ float g_as[cN];
__device__ float g_ad[cN];
__device__ float g_ae1[cE];
__device__ float g_ae2[cE];
__device__ float g_aesum1[cN];
__device__ float g_aesum2[cN];
__device__ float g_aeloop1[cN];
__device__ float g_aeloop2[cN];
__device__ float g_cnt[cN];
__device__ unsigned g_m[cN];         // order-preserving max bits
__device__ float g_denom[cN];
__device__ float g_ex[cE];           // alpha, then exp(alpha - m)
__device__ float g_exloop[cN];
__device__ float g_we[2 * cED];      // We1@att_edge1 | We2@att_edge2

// order-preserving float <-> uint map (any finite float maps to >= 0x00800000,
// so zero-init works as -inf; every node has a self-loop so g_m is always written)
__device__ __forceinline__ unsigned fmap(float f) {
    unsigned u = __float_as_uint(f);
    return (u & 0x80000000u) ? ~u : (u | 0x80000000u);
}
__device__ __forceinline__ float funmap(unsigned v) {
    unsigned u = (v & 0x80000000u) ? (v ^ 0x80000000u) : ~v;
    return __uint_as_float(u);
}

// ---------------- init kernels ----------------
__global__ void k_fill_pre() {
    int i = blockIdx.x * blockDim.x + threadIdx.x;
    if (i < cN) { g_cnt[i] = 0.f; g_aesum1[i] = 0.f; g_aesum2[i] = 0.f; }
}
__global__ void k_fill_layer() {
    int i = blockIdx.x * blockDim.x + threadIdx.x;
    if (i < cN) { g_m[i] = 0u; g_denom[i] = 0.f; }
}

// w_e = We @ att_edge for both layers. 128 threads.
__global__ void k_we(const float* __restrict__ We1, const float* __restrict__ ae1,
                     const float* __restrict__ We2, const float* __restrict__ ae2) {
    int t = threadIdx.x;
    if (t < cED) {
        float s = 0.f;
        for (int k = 0; k < cH; k++) s += We1[t * cH + k] * ae1[k];
        g_we[t] = s;
    } else if (t < 2 * cED) {
        int u = t - cED;
        float s = 0.f;
        for (int k = 0; k < cO; k++) s += We2[u * cO + k] * ae2[k];
        g_we[cED + u] = s;
    }
}

// per-edge a_e for both layers + in-degree + per-dst sums (for self-loop a_e)
__global__ void k_ae(const float* __restrict__ ea, const int* __restrict__ dst) {
    __shared__ float sw[2 * cED];
    int tid = threadIdx.x;
    if (tid < 2 * cED) sw[tid] = g_we[tid];
    __syncthreads();
    int w = (int)((blockIdx.x * (long long)blockDim.x + tid) >> 5);
    int lane = tid & 31;
    if (w >= cE) return;
    float2 v = *reinterpret_cast<const float2*>(ea + (size_t)w * cED + lane * 2);
    float s1 = v.x * sw[lane * 2] + v.y * sw[lane * 2 + 1];
    float s2 = v.x * sw[cED + lane * 2] + v.y * sw[cED + lane * 2 + 1];
#pragma unroll
    for (int o = 16; o > 0; o >>= 1) {
        s1 += __shfl_xor_sync(0xffffffffu, s1, o);
        s2 += __shfl_xor_sync(0xffffffffu, s2, o);
    }
    if (lane == 0) {
        int d = dst[w];
        g_ae1[w] = s1;
        g_ae2[w] = s2;
        atomicAdd(&g_aesum1[d], s1);
        atomicAdd(&g_aesum2[d], s2);
        atomicAdd(&g_cnt[d], 1.f);
    }
}

__global__ void k_aeloop() {
    int i = blockIdx.x * blockDim.x + threadIdx.x;
    if (i < cN) {
        float d = fmaxf(g_cnt[i], 1.f);
        g_aeloop1[i] = g_aesum1[i] / d;
        g_aeloop2[i] = g_aesum2[i] / d;
    }
}

// ---------------- tiled GEMM: out = A[N,K] @ B[K,BN] ----------------
// OUTSEL 0 -> g_h1, 1 -> g_h2. blockDim = 256.
template <int BM, int BN, int BK, int TM, int TN, int K, int OUTSEL>
__global__ void k_gemm(const float* __restrict__ A, const float* __restrict__ B, int Nrows) {
    constexpr int TX = BN / TN;
    constexpr int TY = BM / TM;
    static_assert(TX * TY == 256, "thread layout");
    __shared__ float As[BM][BK];
    __shared__ float Bs[BK][BN];
    float* Cout = (OUTSEL == 0) ? g_h1 : g_h2;

    int tid = threadIdx.x;
    int tx = tid % TX;
    int ty = tid / TX;
    int rowBase = blockIdx.x * BM;

    float acc[TM][TN];
#pragma unroll
    for (int i = 0; i < TM; i++)
#pragma unroll
        for (int j = 0; j < TN; j++) acc[i][j] = 0.f;

    for (int k0 = 0; k0 < K; k0 += BK) {
        constexpr int A4 = BM * BK / 4;
#pragma unroll
        for (int idx = tid; idx < A4; idx += 256) {
            int r = idx / (BK / 4), q = idx % (BK / 4);
            int row = rowBase + r;
            float4 v = make_float4(0.f, 0.f, 0.f, 0.f);
            if (row < Nrows)
                v = *reinterpret_cast<const float4*>(A + (size_t)row * K + k0 + q * 4);
            *reinterpret_cast<float4*>(&As[r][q * 4]) = v;
        }
        constexpr int B4 = BK * BN / 4;
#pragma unroll
        for (int idx = tid; idx < B4; idx += 256) {
            int r = idx / (BN / 4), q = idx % (BN / 4);
            *reinterpret_cast<float4*>(&Bs[r][q * 4]) =
                *reinterpret_cast<const float4*>(B + (size_t)(k0 + r) * BN + q * 4);
        }
        __syncthreads();
#pragma unroll
        for (int kk = 0; kk < BK; kk++) {
            float a[TM], b[TN];
#pragma unroll
            for (int i = 0; i < TM; i++) a[i] = As[ty * TM + i][kk];
#pragma unroll
            for (int j = 0; j < TN; j++) b[j] = Bs[kk][tx + j * TX];
#pragma unroll
            for (int i = 0; i < TM; i++)
#pragma unroll
                for (int j = 0; j < TN; j++) acc[i][j] = fmaf(a[i], b[j], acc[i][j]);
        }
        __syncthreads();
    }
#pragma unroll
    for (int i = 0; i < TM; i++) {
        int row = rowBase + ty * TM + i;
        if (row < Nrows) {
#pragma unroll
            for (int j = 0; j < TN; j++)
                Cout[(size_t)row * BN + tx + j * TX] = acc[i][j];
        }
    }
}

// a_s = h @ att_src, a_d = h @ att_dst. Warp per node.
template <int C, int LAYER>
__global__ void k_asad(const float* __restrict__ asrc, const float* __restrict__ adst) {
    const float* h = (LAYER == 0) ? g_h1 : g_h2;
    int w = (int)((blockIdx.x * (long long)blockDim.x + threadIdx.x) >> 5);
    int lane = threadIdx.x & 31;
    if (w >= cN) return;
    float s = 0.f, d = 0.f;
#pragma unroll
    for (int c = lane; c < C; c += 32) {
        float hv = h[(size_t)w * C + c];
        s += hv * __ldg(asrc + c);
        d += hv * __ldg(adst + c);
    }
#pragma unroll
    for (int o = 16; o > 0; o >>= 1) {
        s += __shfl_xor_sync(0xffffffffu, s, o);
        d += __shfl_xor_sync(0xffffffffu, d, o);
    }
    if (lane == 0) { g_as[w] = s; g_ad[w] = d; }
}

// alpha = leaky_relu(a_s[src]+a_d[dst]+a_e) for E edges + N self-loops; segment max
template <int LAYER>
__global__ void k_alpha(const int* __restrict__ src, const int* __restrict__ dst) {
    const float* ae = (LAYER == 0) ? g_ae1 : g_ae2;
    const float* ael = (LAYER == 0) ? g_aeloop1 : g_aeloop2;
    int i = blockIdx.x * blockDim.x + threadIdx.x;
    if (i < cE) {
        int s = src[i], d = dst[i];
        float a = g_as[s] + g_ad[d] + ae[i];
        a = (a >= 0.f) ? a : NEG * a;
        g_ex[i] = a;
        atomicMax(&g_m[d], fmap(a));
    } else if (i < cE + cN) {
        int n = i - cE;
        float a = g_as[n] + g_ad[n] + ael[n];
        a = (a >= 0.f) ? a : NEG * a;
        g_exloop[n] = a;
        atomicMax(&g_m[n], fmap(a));
    }
}

// ex = exp(alpha - m[dst]); denom = segsum(ex)
__global__ void k_ex(const int* __restrict__ dst) {
    int i = blockIdx.x * blockDim.x + threadIdx.x;
    if (i < cE) {
        int d = dst[i];
        float ex = expf(g_ex[i] - funmap(g_m[d]));
        g_ex[i] = ex;
        atomicAdd(&g_denom[d], ex);
    } else if (i < cE + cN) {
        int n = i - cE;
        float ex = expf(g_exloop[n] - funmap(g_m[n]));
        g_exloop[n] = ex;
        atomicAdd(&g_denom[n], ex);
    }
}

// out = b + coef_selfloop * h[n]  (non-atomic init with bias + self-loop term)
template <int C, int LAYER>
__global__ void k_initout(const float* __restrict__ b, float* __restrict__ out) {
    const float* h = (LAYER == 0) ? g_h1 : g_h2;
    int i = blockIdx.x * blockDim.x + threadIdx.x;
    if (i >= cN * C) return;
    int n = i / C, c = i % C;
    float coef = g_exloop[n] / (g_denom[n] + EPSc);
    out[i] = b[c] + coef * h[i];
}

// out[dst] += coef * h[src], warp per edge
template <int C, int LAYER>
__global__ void k_scatter(const int* __restrict__ src, const int* __restrict__ dst,
                          float* __restrict__ out) {
    const float* h = (LAYER == 0) ? g_h1 : g_h2;
    int w = (int)((blockIdx.x * (long long)blockDim.x + threadIdx.x) >> 5);
    int lane = threadIdx.x & 31;
    if (w >= cE) return;
    int s = src[w], d = dst[w];
    float coef = g_ex[w] / (g_denom[d] + EPSc);
    if (C == 128) {
        float4 v = *reinterpret_cast<const float4*>(h + (size_t)s * C + lane * 4);
        float* o = out + (size_t)d * C + lane * 4;
        atomicAdd(o + 0, coef * v.x);
        atomicAdd(o + 1, coef * v.y);
        atomicAdd(o + 2, coef * v.z);
        atomicAdd(o + 3, coef * v.w);
    } else {
        float v = h[(size_t)s * C + lane];
        atomicAdd(out + (size_t)d * C + lane, coef * v);
    }
}

__global__ void k_relu(float* __restrict__ p, int n) {
    int i = blockIdx.x * blockDim.x + threadIdx.x;
    if (i < n) p[i] = fmaxf(p[i], 0.f);
}

// ---------------- launch ----------------
extern "C" void kernel_launch(void* const* d_in, const int* in_sizes, int n_in,
                              void* d_out, int out_size) {
    (void)in_sizes; (void)n_in; (void)out_size;
    const float* x      = (const float*)d_in[0];
    const int*   ei     = (const int*)d_in[1];
    const float* ea     = (const float*)d_in[2];
    const float* W1     = (const float*)d_in[3];
    const float* asrc1  = (const float*)d_in[4];
    const float* adst1  = (const float*)d_in[5];
    const float* We1    = (const float*)d_in[6];
    const float* aedge1 = (const float*)d_in[7];
    const float* b1     = (const float*)d_in[8];
    const float* W2     = (const float*)d_in[9];
    const float* asrc2  = (const float*)d_in[10];
    const float* adst2  = (const float*)d_in[11];
    const float* We2    = (const float*)d_in[12];
    const float* aedge2 = (const float*)d_in[13];
    const float* b2     = (const float*)d_in[14];

    const int* src = ei;
    const int* dst = ei + cE;

    float* out2 = (float*)d_out;                       // [N, O]
    float* hout = (float*)d_out + (size_t)cN * cO;     // [N, H] = relu(x1)

    const int nb_n   = (cN + 255) / 256;               // node-grain
    const int nb_en  = (cE + cN + 255) / 256;          // edges + self-loops
    const int nb_w   = (cE + 7) / 8;                   // warp-per-edge, 8 warps/block
    const int nb_wn  = (cN + 7) / 8;                   // warp-per-node

    // ---- shared pre-pass ----
    k_fill_pre<<<nb_n, 256>>>();
    k_we<<<1, 128>>>(We1, aedge1, We2, aedge2);
    k_ae<<<nb_w, 256>>>(ea, dst);
    k_aeloop<<<nb_n, 256>>>();

    // ---- layer 1 (F=256 -> H=128) ----
    k_gemm<64, 128, 32, 4, 8, cF, 0><<<(cN + 63) / 64, 256>>>(x, W1, cN);
    k_asad<cH, 0><<<nb_wn, 256>>>(asrc1, adst1);
    k_fill_layer<<<nb_n, 256>>>();
    k_alpha<0><<<nb_en, 256>>>(src, dst);
    k_ex<<<nb_en, 256>>>(dst);
    k_initout<cH, 0><<<(cN * cH + 255) / 256, 256>>>(b1, hout);
    k_scatter<cH, 0><<<nb_w, 256>>>(src, dst, hout);
    k_relu<<<(cN * cH + 255) / 256, 256>>>(hout, cN * cH);

    // ---- layer 2 (H=128 -> O=32) ----
    k_gemm<64, 32, 32, 4, 2, cH, 1><<<(cN + 63) / 64, 256>>>(hout, W2, cN);
    k_asad<cO, 1><<<nb_wn, 256>>>(asrc2, adst2);
    k_fill_layer<<<nb_n, 256>>>();
    k_alpha<1><<<nb_en, 256>>>(src, dst);
    k_ex<<<nb_en, 256>>>(dst);
    k_initout<cO, 1><<<(cN * cO + 255) / 256, 256>>>(b2, out2);
    k_scatter<cO, 1><<<nb_w, 256>>>(src, dst, out2);
}

// round 15
// speedup vs baseline: 1.0076x; 1.0076x over previous
#include <cuda_runtime.h>

#define cN 50000
#define cE 500000
#define cF 256
#define cED 64
#define cH 128
#define cO 32
#define NEG 0.2f
#define EPSc 1e-16f

// ---------------- scratch (device globals; no allocation allowed) ----------------
__device__ float g_h1[cN * cH];      // layer1 h = x@W1
__device__ float g_h2[cN * cO];      // layer2 h = relu(x1)@W2
__device__ float g_as[cN];
__device__ float g_ad[cN];
__device__ float g_ae1[cE];
__device__ float g_ae2[cE];
__device__ float g_aesum1[cN];
__device__ float g_aesum2[cN];
__device__ float g_aeloop1[cN];
__device__ float g_aeloop2[cN];
__device__ float g_cnt[cN];
__device__ unsigned g_m[cN];         // order-preserving max bits
__device__ float g_denom[cN];
__device__ float g_ex[cE];           // alpha, then exp(alpha - m)
__device__ float g_exloop[cN];
__device__ float g_we[2 * cED];      // We1@att_edge1 | We2@att_edge2

// order-preserving float <-> uint map (any finite float maps to >= 0x00800000,
// so zero-init works as -inf; every node has a self-loop so g_m is always written)
__device__ __forceinline__ unsigned fmap(float f) {
    unsigned u = __float_as_uint(f);
    return (u & 0x80000000u) ? ~u : (u | 0x80000000u);
}
__device__ __forceinline__ float funmap(unsigned v) {
    unsigned u = (v & 0x80000000u) ? (v ^ 0x80000000u) : ~v;
    return __uint_as_float(u);
}

// ---------------- init kernels ----------------
__global__ void k_fill_pre() {
    int i = blockIdx.x * blockDim.x + threadIdx.x;
    if (i < cN) { g_cnt[i] = 0.f; g_aesum1[i] = 0.f; g_aesum2[i] = 0.f; }
}
__global__ void k_fill_layer() {
    int i = blockIdx.x * blockDim.x + threadIdx.x;
    if (i < cN) { g_m[i] = 0u; g_denom[i] = 0.f; }
}

// w_e = We @ att_edge for both layers. 128 threads.
__global__ void k_we(const float* __restrict__ We1, const float* __restrict__ ae1,
                     const float* __restrict__ We2, const float* __restrict__ ae2) {
    int t = threadIdx.x;
    if (t < cED) {
        float s = 0.f;
        for (int k = 0; k < cH; k++) s += We1[t * cH + k] * ae1[k];
        g_we[t] = s;
    } else if (t < 2 * cED) {
        int u = t - cED;
        float s = 0.f;
        for (int k = 0; k < cO; k++) s += We2[u * cO + k] * ae2[k];
        g_we[cED + u] = s;
    }
}

// per-edge a_e for both layers + in-degree + per-dst sums (for self-loop a_e)
__global__ void k_ae(const float* __restrict__ ea, const int* __restrict__ dst) {
    __shared__ float sw[2 * cED];
    int tid = threadIdx.x;
    if (tid < 2 * cED) sw[tid] = g_we[tid];
    __syncthreads();
    int w = (int)((blockIdx.x * (long long)blockDim.x + tid) >> 5);
    int lane = tid & 31;
    if (w >= cE) return;
    float2 v = *reinterpret_cast<const float2*>(ea + (size_t)w * cED + lane * 2);
    float s1 = v.x * sw[lane * 2] + v.y * sw[lane * 2 + 1];
    float s2 = v.x * sw[cED + lane * 2] + v.y * sw[cED + lane * 2 + 1];
#pragma unroll
    for (int o = 16; o > 0; o >>= 1) {
        s1 += __shfl_xor_sync(0xffffffffu, s1, o);
        s2 += __shfl_xor_sync(0xffffffffu, s2, o);
    }
    if (lane == 0) {
        int d = dst[w];
        g_ae1[w] = s1;
        g_ae2[w] = s2;
        atomicAdd(&g_aesum1[d], s1);
        atomicAdd(&g_aesum2[d], s2);
        atomicAdd(&g_cnt[d], 1.f);
    }
}

__global__ void k_aeloop() {
    int i = blockIdx.x * blockDim.x + threadIdx.x;
    if (i < cN) {
        float d = fmaxf(g_cnt[i], 1.f);
        g_aeloop1[i] = g_aesum1[i] / d;
        g_aeloop2[i] = g_aesum2[i] / d;
    }
}

// ---------------- tiled GEMM: out = A[N,K] @ B[K,BN] ----------------
// OUTSEL 0 -> g_h1, 1 -> g_h2. blockDim = 256.
template <int BM, int BN, int BK, int TM, int TN, int K, int OUTSEL>
__global__ void k_gemm(const float* __restrict__ A, const float* __restrict__ B, int Nrows) {
    constexpr int TX = BN / TN;
    constexpr int TY = BM / TM;
    static_assert(TX * TY == 256, "thread layout");
    __shared__ float As[BM][BK];
    __shared__ float Bs[BK][BN];
    float* Cout = (OUTSEL == 0) ? g_h1 : g_h2;

    int tid = threadIdx.x;
    int tx = tid % TX;
    int ty = tid / TX;
    int rowBase = blockIdx.x * BM;

    float acc[TM][TN];
#pragma unroll
    for (int i = 0; i < TM; i++)
#pragma unroll
        for (int j = 0; j < TN; j++) acc[i][j] = 0.f;

    for (int k0 = 0; k0 < K; k0 += BK) {
        constexpr int A4 = BM * BK / 4;
#pragma unroll
        for (int idx = tid; idx < A4; idx += 256) {
            int r = idx / (BK / 4), q = idx % (BK / 4);
            int row = rowBase + r;
            float4 v = make_float4(0.f, 0.f, 0.f, 0.f);
            if (row < Nrows)
                v = *reinterpret_cast<const float4*>(A + (size_t)row * K + k0 + q * 4);
            *reinterpret_cast<float4*>(&As[r][q * 4]) = v;
        }
        constexpr int B4 = BK * BN / 4;
#pragma unroll
        for (int idx = tid; idx < B4; idx += 256) {
            int r = idx / (BN / 4), q = idx % (BN / 4);
            *reinterpret_cast<float4*>(&Bs[r][q * 4]) =
                *reinterpret_cast<const float4*>(B + (size_t)(k0 + r) * BN + q * 4);
        }
        __syncthreads();
#pragma unroll
        for (int kk = 0; kk < BK; kk++) {
            float a[TM], b[TN];
#pragma unroll
            for (int i = 0; i < TM; i++) a[i] = As[ty * TM + i][kk];
#pragma unroll
            for (int j = 0; j < TN; j++) b[j] = Bs[kk][tx + j * TX];
#pragma unroll
            for (int i = 0; i < TM; i++)
#pragma unroll
                for (int j = 0; j < TN; j++) acc[i][j] = fmaf(a[i], b[j], acc[i][j]);
        }
        __syncthreads();
    }
#pragma unroll
    for (int i = 0; i < TM; i++) {
        int row = rowBase + ty * TM + i;
        if (row < Nrows) {
#pragma unroll
            for (int j = 0; j < TN; j++)
                Cout[(size_t)row * BN + tx + j * TX] = acc[i][j];
        }
    }
}

// a_s = h @ att_src, a_d = h @ att_dst. Warp per node.
template <int C, int LAYER>
__global__ void k_asad(const float* __restrict__ asrc, const float* __restrict__ adst) {
    const float* h = (LAYER == 0) ? g_h1 : g_h2;
    int w = (int)((blockIdx.x * (long long)blockDim.x + threadIdx.x) >> 5);
    int lane = threadIdx.x & 31;
    if (w >= cN) return;
    float s = 0.f, d = 0.f;
#pragma unroll
    for (int c = lane; c < C; c += 32) {
        float hv = h[(size_t)w * C + c];
        s += hv * __ldg(asrc + c);
        d += hv * __ldg(adst + c);
    }
#pragma unroll
    for (int o = 16; o > 0; o >>= 1) {
        s += __shfl_xor_sync(0xffffffffu, s, o);
        d += __shfl_xor_sync(0xffffffffu, d, o);
    }
    if (lane == 0) { g_as[w] = s; g_ad[w] = d; }
}

// alpha = leaky_relu(a_s[src]+a_d[dst]+a_e) for E edges + N self-loops; segment max
template <int LAYER>
__global__ void k_alpha(const int* __restrict__ src, const int* __restrict__ dst) {
    const float* ae = (LAYER == 0) ? g_ae1 : g_ae2;
    const float* ael = (LAYER == 0) ? g_aeloop1 : g_aeloop2;
    int i = blockIdx.x * blockDim.x + threadIdx.x;
    if (i < cE) {
        int s = src[i], d = dst[i];
        float a = g_as[s] + g_ad[d] + ae[i];
        a = (a >= 0.f) ? a : NEG * a;
        g_ex[i] = a;
        atomicMax(&g_m[d], fmap(a));
    } else if (i < cE + cN) {
        int n = i - cE;
        float a = g_as[n] + g_ad[n] + ael[n];
        a = (a >= 0.f) ? a : NEG * a;
        g_exloop[n] = a;
        atomicMax(&g_m[n], fmap(a));
    }
}

// ex = exp(alpha - m[dst]); denom = segsum(ex)
__global__ void k_ex(const int* __restrict__ dst) {
    int i = blockIdx.x * blockDim.x + threadIdx.x;
    if (i < cE) {
        int d = dst[i];
        float ex = expf(g_ex[i] - funmap(g_m[d]));
        g_ex[i] = ex;
        atomicAdd(&g_denom[d], ex);
    } else if (i < cE + cN) {
        int n = i - cE;
        float ex = expf(g_exloop[n] - funmap(g_m[n]));
        g_exloop[n] = ex;
        atomicAdd(&g_denom[n], ex);
    }
}

// out = b + coef_selfloop * h[n]  (non-atomic init with bias + self-loop term)
template <int C, int LAYER>
__global__ void k_initout(const float* __restrict__ b, float* __restrict__ out) {
    const float* h = (LAYER == 0) ? g_h1 : g_h2;
    int i = blockIdx.x * blockDim.x + threadIdx.x;
    if (i >= cN * C) return;
    int n = i / C, c = i % C;
    float coef = g_exloop[n] / (g_denom[n] + EPSc);
    out[i] = b[c] + coef * h[i];
}

// out[dst] += coef * h[src], warp per edge
template <int C, int LAYER>
__global__ void k_scatter(const int* __restrict__ src, const int* __restrict__ dst,
                          float* __restrict__ out) {
    const float* h = (LAYER == 0) ? g_h1 : g_h2;
    int w = (int)((blockIdx.x * (long long)blockDim.x + threadIdx.x) >> 5);
    int lane = threadIdx.x & 31;
    if (w >= cE) return;
    int s = src[w], d = dst[w];
    float coef = g_ex[w] / (g_denom[d] + EPSc);
    if (C == 128) {
        float4 v = *reinterpret_cast<const float4*>(h + (size_t)s * C + lane * 4);
        float* o = out + (size_t)d * C + lane * 4;
        atomicAdd(o + 0, coef * v.x);
        atomicAdd(o + 1, coef * v.y);
        atomicAdd(o + 2, coef * v.z);
        atomicAdd(o + 3, coef * v.w);
    } else {
        float v = h[(size_t)s * C + lane];
        atomicAdd(out + (size_t)d * C + lane, coef * v);
    }
}

__global__ void k_relu(float* __restrict__ p, int n) {
    int i = blockIdx.x * blockDim.x + threadIdx.x;
    if (i < n) p[i] = fmaxf(p[i], 0.f);
}

// ---------------- launch ----------------
extern "C" void kernel_launch(void* const* d_in, const int* in_sizes, int n_in,
                              void* d_out, int out_size) {
    (void)in_sizes; (void)n_in; (void)out_size;
    const float* x      = (const float*)d_in[0];
    const int*   ei     = (const int*)d_in[1];
    const float* ea     = (const float*)d_in[2];
    const float* W1     = (const float*)d_in[3];
    const float* asrc1  = (const float*)d_in[4];
    const float* adst1  = (const float*)d_in[5];
    const float* We1    = (const float*)d_in[6];
    const float* aedge1 = (const float*)d_in[7];
    const float* b1     = (const float*)d_in[8];
    const float* W2     = (const float*)d_in[9];
    const float* asrc2  = (const float*)d_in[10];
    const float* adst2  = (const float*)d_in[11];
    const float* We2    = (const float*)d_in[12];
    const float* aedge2 = (const float*)d_in[13];
    const float* b2     = (const float*)d_in[14];

    const int* src = ei;
    const int* dst = ei + cE;

    float* out2 = (float*)d_out;                       // [N, O]
    float* hout = (float*)d_out + (size_t)cN * cO;     // [N, H] = relu(x1)

    const int nb_n   = (cN + 255) / 256;               // node-grain
    const int nb_en  = (cE + cN + 255) / 256;          // edges + self-loops
    const int nb_w   = (cE + 7) / 8;                   // warp-per-edge, 8 warps/block
    const int nb_wn  = (cN + 7) / 8;                   // warp-per-node

    // ---- shared pre-pass ----
    k_fill_pre<<<nb_n, 256>>>();
    k_we<<<1, 128>>>(We1, aedge1, We2, aedge2);
    k_ae<<<nb_w, 256>>>(ea, dst);
    k_aeloop<<<nb_n, 256>>>();

    // ---- layer 1 (F=256 -> H=128) ----
    k_gemm<64, 128, 32, 4, 8, cF, 0><<<(cN + 63) / 64, 256>>>(x, W1, cN);
    k_asad<cH, 0><<<nb_wn, 256>>>(asrc1, adst1);
    k_fill_layer<<<nb_n, 256>>>();
    k_alpha<0><<<nb_en, 256>>>(src, dst);
    k_ex<<<nb_en, 256>>>(dst);
    k_initout<cH, 0><<<(cN * cH + 255) / 256, 256>>>(b1, hout);
    k_scatter<cH, 0><<<nb_w, 256>>>(src, dst, hout);
    k_relu<<<(cN * cH + 255) / 256, 256>>>(hout, cN * cH);

    // ---- layer 2 (H=128 -> O=32) ----
    k_gemm<64, 32, 32, 4, 2, cH, 1><<<(cN + 63) / 64, 256>>>(hout, W2, cN);
    k_asad<cO, 1><<<nb_wn, 256>>>(asrc2, adst2);
    k_fill_layer<<<nb_n, 256>>>();
    k_alpha<1><<<nb_en, 256>>>(src, dst);
    k_ex<<<nb_en, 256>>>(dst);
    k_initout<cO, 1><<<(cN * cO + 255) / 256, 256>>>(b2, out2);
    k_scatter<cO, 1><<<nb_w, 256>>>(src, dst, out2);
}